// round 2
// baseline (speedup 1.0000x reference)
#include <cuda_runtime.h>
#include <math.h>
#include <stdint.h>

#define S_DIM 32
#define A_DIM 4
#define F1    36     // S+A
#define H1    64
#define F2    7      // A+3
#define H2    32
#define MAXK  16384

// ---------------- scratch (allocation-free: __device__ globals) ----------------
__device__ float g_cnt[MAXK];          // counts
__device__ float g_sumA[MAXK * A_DIM]; // sum arch
__device__ float g_ssq[MAXK * A_DIM];  // sum arch^2
__device__ float g_sumS[MAXK];         // sum surprise
__device__ float g_sume[MAXK];         // sum exp(w)
__device__ float g_sumeA[MAXK * A_DIM];// sum exp(w)*arch
__device__ float g_impc[MAXK];         // cluster importance (-inf if empty)

// ---------------- warp segmented sum (seg_ids sorted => contiguous groups) ----
__device__ __forceinline__ float segSum(float v, int rel, int sz) {
#pragma unroll
    for (int off = 16; off > 0; off >>= 1) {
        float t = __shfl_down_sync(0xffffffffu, v, off);
        if (rel + off < sz) v += t;
    }
    return v;
}

// ---------------- kernel 0: zero accumulators ----------------
__global__ void zeroK(int K) {
    int k = blockIdx.x * blockDim.x + threadIdx.x;
    if (k < K) {
        g_cnt[k] = 0.f;
        g_sumS[k] = 0.f;
        g_sume[k] = 0.f;
#pragma unroll
        for (int a = 0; a < A_DIM; a++) {
            g_sumA[k * A_DIM + a] = 0.f;
            g_ssq[k * A_DIM + a] = 0.f;
            g_sumeA[k * A_DIM + a] = 0.f;
        }
    }
}

// ---------------- pass A: fused per-cell MLP + ALL segmented accumulators ----------------
__global__ void __launch_bounds__(256) passA(
    const float* __restrict__ state, const float* __restrict__ arch,
    const float* __restrict__ energy, const float* __restrict__ phi_local,
    const float* __restrict__ surprise, const int* __restrict__ seg_ids,
    const float* __restrict__ W1, const float* __restrict__ b1,
    const float* __restrict__ W2, const float* __restrict__ b2, int N)
{
    __shared__ __align__(16) float s_w1t[H1 * F1];  // transposed: [j][i], 36 floats/row (144B, 16B-aligned)
    __shared__ float s_b1[H1], s_w2[H1];
    __shared__ float s_b2;
    int t = threadIdx.x;
    for (int idx = t; idx < F1 * H1; idx += 256) {
        int i = idx >> 6, j = idx & 63;        // W1 is [36,64] row-major
        s_w1t[j * F1 + i] = W1[idx];
    }
    if (t < H1) { s_b1[t] = b1[t]; s_w2[t] = W2[t]; }
    if (t == 0) s_b2 = b2[0];
    __syncthreads();

    int cell = blockIdx.x * 256 + t;
    bool active = cell < N;
    int cc = active ? cell : (N - 1);

    float feats[F1];
    const float4* sp = reinterpret_cast<const float4*>(state + (size_t)cc * S_DIM);
#pragma unroll
    for (int q = 0; q < 8; q++) {
        float4 v = sp[q];
        feats[4 * q + 0] = v.x; feats[4 * q + 1] = v.y;
        feats[4 * q + 2] = v.z; feats[4 * q + 3] = v.w;
    }
    float4 av = *reinterpret_cast<const float4*>(arch + (size_t)cc * A_DIM);
    feats[32] = av.x; feats[33] = av.y; feats[34] = av.z; feats[35] = av.w;

    float acc = 0.f;
#pragma unroll 4
    for (int j = 0; j < H1; j++) {
        const float4* wr = reinterpret_cast<const float4*>(s_w1t + j * F1);
        float h = s_b1[j];
#pragma unroll
        for (int q = 0; q < 9; q++) {
            float4 wv = wr[q];
            h = fmaf(feats[4 * q + 0], wv.x, h);
            h = fmaf(feats[4 * q + 1], wv.y, h);
            h = fmaf(feats[4 * q + 2], wv.z, h);
            h = fmaf(feats[4 * q + 3], wv.w, h);
        }
        acc = fmaf(fmaxf(h, 0.f), s_w2[j], acc);
    }

    float ep   = energy[cc] * phi_local[cc];
    float base = 1.f / (1.f + expf(-(acc + s_b2)));
    float imp  = fminf(fmaxf(base * ep, 0.01f), 1.f);
    float w    = imp * ep;                   // w in (0, 1]
    float e    = expf(w);                    // stable: exp in (1, e]; ratios match exp(w-m)

    int seg = seg_ids[cc];
    float one = active ? 1.f : 0.f;
    float sa0 = active ? av.x : 0.f, sa1 = active ? av.y : 0.f;
    float sa2 = active ? av.z : 0.f, sa3 = active ? av.w : 0.f;
    float q0 = sa0 * av.x, q1 = sa1 * av.y, q2 = sa2 * av.z, q3 = sa3 * av.w;
    float su = active ? surprise[cc] : 0.f;
    float ev = active ? e : 0.f;
    float e0 = ev * av.x, e1 = ev * av.y, e2 = ev * av.z, e3 = ev * av.w;

    int lane = t & 31;
    unsigned peers = __match_any_sync(0xffffffffu, seg);
    int leader = __ffs(peers) - 1;
    int rel = lane - leader;
    int sz  = __popc(peers);

    one = segSum(one, rel, sz);
    sa0 = segSum(sa0, rel, sz); sa1 = segSum(sa1, rel, sz);
    sa2 = segSum(sa2, rel, sz); sa3 = segSum(sa3, rel, sz);
    q0  = segSum(q0, rel, sz);  q1  = segSum(q1, rel, sz);
    q2  = segSum(q2, rel, sz);  q3  = segSum(q3, rel, sz);
    su  = segSum(su, rel, sz);
    ev  = segSum(ev, rel, sz);
    e0  = segSum(e0, rel, sz);  e1  = segSum(e1, rel, sz);
    e2  = segSum(e2, rel, sz);  e3  = segSum(e3, rel, sz);

    if (lane == leader) {
        atomicAdd(&g_cnt[seg], one);
        atomicAdd(&g_sumA[seg * 4 + 0], sa0);
        atomicAdd(&g_sumA[seg * 4 + 1], sa1);
        atomicAdd(&g_sumA[seg * 4 + 2], sa2);
        atomicAdd(&g_sumA[seg * 4 + 3], sa3);
        atomicAdd(&g_ssq[seg * 4 + 0], q0);
        atomicAdd(&g_ssq[seg * 4 + 1], q1);
        atomicAdd(&g_ssq[seg * 4 + 2], q2);
        atomicAdd(&g_ssq[seg * 4 + 3], q3);
        atomicAdd(&g_sumS[seg], su);
        atomicAdd(&g_sume[seg], ev);
        atomicAdd(&g_sumeA[seg * 4 + 0], e0);
        atomicAdd(&g_sumeA[seg * 4 + 1], e1);
        atomicAdd(&g_sumeA[seg * 4 + 2], e2);
        atomicAdd(&g_sumeA[seg * 4 + 3], e3);
    }
}

// ---------------- pass C: per-cluster finalize + cluster MLP ----------------
__global__ void __launch_bounds__(256) passC(
    const float* __restrict__ V1, const float* __restrict__ c1,
    const float* __restrict__ V2, const float* __restrict__ c2,
    float* __restrict__ out, int K)
{
    __shared__ float s_v1t[H2 * F2];   // [j][i]
    __shared__ float s_c1[H2], s_v2[H2];
    __shared__ float s_c2;
    int t = threadIdx.x;
    if (t < F2 * H2) {                 // V1 is [7,32] row-major
        int i = t / H2, j = t % H2;
        s_v1t[j * F2 + i] = V1[t];
    }
    if (t < H2) { s_c1[t] = c1[t]; s_v2[t] = V2[t]; }
    if (t == 0) s_c2 = c2[0];
    __syncthreads();

    int k = blockIdx.x * 256 + t;
    if (k >= K) return;

    float cntr = g_cnt[k];
    bool valid = cntr > 0.f;
    float se = g_sume[k];

    float agg[A_DIM];
#pragma unroll
    for (int a = 0; a < A_DIM; a++)
        agg[a] = valid ? g_sumeA[k * 4 + a] / se : 0.f;

    // softmax over archetypes
    float mA = fmaxf(fmaxf(agg[0], agg[1]), fmaxf(agg[2], agg[3]));
    float ea[A_DIM], esum = 0.f;
#pragma unroll
    for (int a = 0; a < A_DIM; a++) { ea[a] = expf(agg[a] - mA); esum += ea[a]; }
    float aggr[A_DIM];
#pragma unroll
    for (int a = 0; a < A_DIM; a++) aggr[a] = ea[a] / esum;

    float cntc = fmaxf(cntr, 1.f);
    float dv   = fmaxf(cntr - 1.f, 1.f);
    float varsum = 0.f;
#pragma unroll
    for (int a = 0; a < A_DIM; a++) {
        float mean = g_sumA[k * 4 + a] / cntc;
        varsum += (g_ssq[k * 4 + a] - cntr * mean * mean) / dv;
    }
    float var_m   = varsum * 0.25f;
    float phi_c   = 1.f - fminf(1.f, var_m * 2.f);
    float coh     = 1.f - var_m;
    float pred_err = g_sumS[k] / cntc;
    float integ   = phi_c * (1.f - pred_err);

    float cfeat[F2] = { aggr[0], aggr[1], aggr[2], aggr[3],
                        phi_c, coh, fminf(1.f, cntr * (1.f / 20.f)) };
    float acc = 0.f;
#pragma unroll
    for (int j = 0; j < H2; j++) {
        float h = s_c1[j];
#pragma unroll
        for (int i = 0; i < F2; i++) h = fmaf(cfeat[i], s_v1t[j * F2 + i], h);
        acc = fmaf(fmaxf(h, 0.f), s_v2[j], acc);
    }
    float basec = 1.f / (1.f + expf(-(acc + s_c2)));
    float impc  = fminf(fmaxf(basec * phi_c, 0.01f), 1.f);

    float* row = out + (size_t)k * 8;
    row[0] = aggr[0]; row[1] = aggr[1]; row[2] = aggr[2]; row[3] = aggr[3];
    row[4] = phi_c; row[5] = coh; row[6] = pred_err; row[7] = integ;

    g_impc[k] = valid ? impc : -INFINITY;
}

// ---------------- finalize: cluster softmax + global self-model ----------------
__device__ __forceinline__ float blkSum(float v, float* sbuf) {
    int t = threadIdx.x;
    __syncthreads(); sbuf[t] = v; __syncthreads();
    for (int s = blockDim.x >> 1; s > 0; s >>= 1) {
        if (t < s) sbuf[t] += sbuf[t + s];
        __syncthreads();
    }
    float r = sbuf[0]; __syncthreads(); return r;
}
__device__ __forceinline__ float blkMax(float v, float* sbuf) {
    int t = threadIdx.x;
    __syncthreads(); sbuf[t] = v; __syncthreads();
    for (int s = blockDim.x >> 1; s > 0; s >>= 1) {
        if (t < s) sbuf[t] = fmaxf(sbuf[t], sbuf[t + s]);
        __syncthreads();
    }
    float r = sbuf[0]; __syncthreads(); return r;
}
__device__ __forceinline__ int blkOr(int v, int* sbuf) {
    int t = threadIdx.x;
    __syncthreads(); sbuf[t] = v; __syncthreads();
    for (int s = blockDim.x >> 1; s > 0; s >>= 1) {
        if (t < s) sbuf[t] |= sbuf[t + s];
        __syncthreads();
    }
    int r = sbuf[0]; __syncthreads(); return r;
}

__global__ void finalize(float* __restrict__ out, int K) {
    __shared__ float sred[1024];
    __shared__ int sredi[1024];
    int t = threadIdx.x;

    // phase 1: max impc (valid only; invalid are -inf) and n_valid
    float mx = -INFINITY, nv = 0.f;
    for (int k = t; k < K; k += 1024) {
        float ic = g_impc[k];
        mx = fmaxf(mx, ic);
        if (ic != -INFINITY) nv += 1.f;
    }
    mx = blkMax(mx, sred);
    nv = blkSum(nv, sred);

    // phase 2: softmax-weighted sums
    float se = 0.f, ga0 = 0.f, ga1 = 0.f, ga2 = 0.f, ga3 = 0.f;
    float sphi = 0.f, scoh = 0.f;
    int mask = 0;
    for (int k = t; k < K; k += 1024) {
        float ic = g_impc[k];
        const float* row = out + (size_t)k * 8;
        float a0 = row[0], a1 = row[1], a2 = row[2], a3 = row[3];
        float u = expf(ic - mx);   // expf(-inf) = 0 for invalid
        se += u;
        ga0 += u * a0; ga1 += u * a1; ga2 += u * a2; ga3 += u * a3;
        if (ic != -INFINITY) {
            sphi += row[4];
            scoh += row[5];
            int spec = 0; float bm = a0;
            if (a1 > bm) { bm = a1; spec = 1; }
            if (a2 > bm) { bm = a2; spec = 2; }
            if (a3 > bm) { bm = a3; spec = 3; }
            mask |= 1 << spec;
        }
    }
    se   = blkSum(se, sred);
    ga0  = blkSum(ga0, sred); ga1 = blkSum(ga1, sred);
    ga2  = blkSum(ga2, sred); ga3 = blkSum(ga3, sred);
    sphi = blkSum(sphi, sred);
    scoh = blkSum(scoh, sred);
    mask = blkOr(mask, sredi);

    if (t == 0) {
        float nvalid = fmaxf(nv, 1.f);
        float g0 = ga0 / se, g1 = ga1 / se, g2 = ga2 / se, g3 = ga3 / se;
        float gm = fmaxf(fmaxf(g0, g1), fmaxf(g2, g3));
        float e0 = expf(g0 - gm), e1 = expf(g1 - gm), e2 = expf(g2 - gm), e3 = expf(g3 - gm);
        float gs = e0 + e1 + e2 + e3;
        float* tail = out + (size_t)K * 8;
        tail[0] = e0 / gs; tail[1] = e1 / gs; tail[2] = e2 / gs; tail[3] = e3 / gs;
        float avg_phi = sphi / nvalid;
        float vert    = scoh / nvalid;
        float unique  = (float)__popc((unsigned)mask);
        tail[4] = fminf(1.f, avg_phi * (0.5f + 0.5f * unique / 4.f));
        tail[5] = vert;
    }
}

// ---------------- launch ----------------
extern "C" void kernel_launch(void* const* d_in, const int* in_sizes, int n_in,
                              void* d_out, int out_size) {
    const float* state     = (const float*)d_in[0];
    const float* arch      = (const float*)d_in[1];
    const float* energy    = (const float*)d_in[2];
    const float* phi_local = (const float*)d_in[3];
    const float* surprise  = (const float*)d_in[4];
    const int*   seg_ids   = (const int*)d_in[5];
    // d_in[6] = n_clusters (device scalar) — K derived from out_size instead (no sync copies allowed)
    const float* W1 = (const float*)d_in[7];
    const float* b1 = (const float*)d_in[8];
    const float* W2 = (const float*)d_in[9];
    const float* b2 = (const float*)d_in[10];
    const float* V1 = (const float*)d_in[11];
    const float* c1 = (const float*)d_in[12];
    const float* V2 = (const float*)d_in[13];
    const float* c2 = (const float*)d_in[14];

    int N = in_sizes[2];                       // energy element count
    int K = (out_size - (A_DIM + 2)) / (A_DIM + 4);
    float* out = (float*)d_out;

    int gN = (N + 255) / 256;
    int gK = (K + 255) / 256;

    zeroK<<<gK, 256>>>(K);
    passA<<<gN, 256>>>(state, arch, energy, phi_local, surprise, seg_ids,
                       W1, b1, W2, b2, N);
    passC<<<gK, 256>>>(V1, c1, V2, c2, out, K);
    finalize<<<1, 1024>>>(out, K);
}